// round 4
// baseline (speedup 1.0000x reference)
#include <cuda_runtime.h>

#define MM 4096
#define NN 4096
#define PLANE (MM * NN)
#define MAX_IT 20
#define F_SIGMA 14.285714285714285f   // 1/(7*0.01)
#define F_TAU 0.01f
#define F_LT 0.07f                    // LAMBDA_ROF * TAU
#define F_THETA 0.5f
#define F_INV_DENOM (1.0f / 1.07f)

#define TS 32          // output tile
#define ES 36          // tile + 2*halo(2)
#define NTHREADS 1024

// Ping-pong scratch (allocation-free rule: __device__ globals)
__device__ float g_x[2][PLANE];
__device__ float g_xt[2][PLANE];
__device__ float g_y[2][2 * PLANE];

__device__ __forceinline__ float clip1(float v) {
    return fminf(fmaxf(v, -1.0f), 1.0f);
}

// Two fused primal-dual iterations per kernel, smem-tiled with halo 2.
// Local coords l in [-2, 34); smem index c = (li+2)*ES + (lj+2).
// Phases (each separated by __syncthreads):
//   1a: y'  on l in [-2,33)  (in-place over s_y0/s_y1)
//   1b: x', xt' on l in [-1,33)  (x' in-place over s_x, xt' over s_xt)
//   2a: y'' on l in [-1,32)  (in-place; tile part written to gmem)
//   2b: x'', xt'' on tile, written to gmem
__global__ __launch_bounds__(NTHREADS) void pd_iter2(
    int first, int last, int in_b, int out_b,
    const float* __restrict__ img,
    const float* __restrict__ w,
    const float* __restrict__ y0p,
    float* __restrict__ dout)
{
    __shared__ float s_xt[ES * ES];
    __shared__ float s_x [ES * ES];
    __shared__ float s_y0[ES * ES];
    __shared__ float s_y1[ES * ES];
    __shared__ float s_w0[ES * ES];
    __shared__ float s_w1[ES * ES];
    __shared__ float s_im[ES * ES];

    const int tid = threadIdx.x;
    const int gi0 = blockIdx.y * TS;
    const int gj0 = blockIdx.x * TS;

    const float* __restrict__ xt_in = first ? img : g_xt[in_b];
    const float* __restrict__ x_in  = first ? img : g_x[in_b];
    const float* __restrict__ y0_in = first ? y0p : g_y[in_b];
    const float* __restrict__ y1_in = first ? (y0p + PLANE) : (g_y[in_b] + PLANE);
    const float* __restrict__ w0 = w;
    const float* __restrict__ w1 = w + PLANE;
    float* __restrict__ x_out  = g_x[out_b];
    float* __restrict__ xt_out = last ? dout : g_xt[out_b];
    float* __restrict__ y_out  = g_y[out_b];

    // ---- load phase: xt on [-2,34); y,w on [-2,33); x,img on [-1,33)
    for (int t = tid; t < ES * ES; t += NTHREADS) {
        const int li = t / ES - 2;
        const int lj = t % ES - 2;
        const int gi = gi0 + li, gj = gj0 + lj;
        const bool in = ((unsigned)gi < MM) && ((unsigned)gj < NN);
        const int g = gi * NN + gj;
        s_xt[t] = in ? xt_in[g] : 0.0f;
        if (li < 33 && lj < 33) {
            s_y0[t] = in ? y0_in[g] : 0.0f;
            s_y1[t] = in ? y1_in[g] : 0.0f;
            s_w0[t] = in ? w0[g] : 0.0f;
            s_w1[t] = in ? w1[g] : 0.0f;
            if (li >= -1 && lj >= -1) {
                s_x[t]  = in ? x_in[g] : 0.0f;
                s_im[t] = in ? img[g]  : 0.0f;
            }
        }
    }
    __syncthreads();

    // ---- phase 1a: dual update (iteration 1), y' on 35x35, in-place
    for (int t = tid; t < 35 * 35; t += NTHREADS) {
        const int li = t / 35 - 2, lj = t % 35 - 2;
        const int gi = gi0 + li, gj = gj0 + lj;
        const int c = (li + 2) * ES + (lj + 2);
        const float xtc = s_xt[c];
        const float gx = (gj < NN - 1) ? (s_xt[c + 1]  - xtc) : 0.0f;
        const float gy = (gi < MM - 1) ? (s_xt[c + ES] - xtc) : 0.0f;
        s_y0[c] = clip1(s_y0[c] + F_SIGMA * s_w0[c] * gx);
        s_y1[c] = clip1(s_y1[c] + F_SIGMA * s_w1[c] * gy);
    }
    __syncthreads();

    // ---- phase 1b: primal + relax (iteration 1), x'/xt' on 34x34, in-place
    for (int t = tid; t < 34 * 34; t += NTHREADS) {
        const int li = t / 34 - 1, lj = t % 34 - 1;
        const int gi = gi0 + li, gj = gj0 + lj;
        const int c = (li + 2) * ES + (lj + 2);
        const float h_c = s_w0[c] * s_y0[c];
        const float v_c = s_w1[c] * s_y1[c];
        float dh;
        if (gj == 0) dh = h_c;
        else {
            const float h_l = s_w0[c - 1] * s_y0[c - 1];
            dh = (gj == NN - 1) ? -h_l : (h_c - h_l);
        }
        float dv;
        if (gi == 0) dv = v_c;
        else {
            const float v_u = s_w1[c - ES] * s_y1[c - ES];
            dv = (gi == MM - 1) ? -v_u : (v_c - v_u);
        }
        const float xo = s_x[c];
        const float xn = (xo + F_TAU * (dh + dv) + F_LT * s_im[c]) * F_INV_DENOM;
        s_x[c]  = xn;
        s_xt[c] = xn + F_THETA * (xn - xo);   // raw xt dead after phase 1a
    }
    __syncthreads();

    // ---- phase 2a: dual update (iteration 2), y'' on 33x33, in-place;
    //      tile part streamed to gmem
    for (int t = tid; t < 33 * 33; t += NTHREADS) {
        const int li = t / 33 - 1, lj = t % 33 - 1;
        const int gi = gi0 + li, gj = gj0 + lj;
        const int c = (li + 2) * ES + (lj + 2);
        const float xtc = s_xt[c];
        const float gx = (gj < NN - 1) ? (s_xt[c + 1]  - xtc) : 0.0f;
        const float gy = (gi < MM - 1) ? (s_xt[c + ES] - xtc) : 0.0f;
        const float y0n = clip1(s_y0[c] + F_SIGMA * s_w0[c] * gx);
        const float y1n = clip1(s_y1[c] + F_SIGMA * s_w1[c] * gy);
        s_y0[c] = y0n;
        s_y1[c] = y1n;
        if (li >= 0 && lj >= 0) {
            const int g = gi * NN + gj;
            y_out[g]         = y0n;
            y_out[g + PLANE] = y1n;
        }
    }
    __syncthreads();

    // ---- phase 2b: primal + relax (iteration 2) on the 32x32 tile
    {
        const int li = tid / 32, lj = tid % 32;
        const int gi = gi0 + li, gj = gj0 + lj;
        const int c = (li + 2) * ES + (lj + 2);
        const float h_c = s_w0[c] * s_y0[c];
        const float v_c = s_w1[c] * s_y1[c];
        float dh;
        if (gj == 0) dh = h_c;
        else {
            const float h_l = s_w0[c - 1] * s_y0[c - 1];
            dh = (gj == NN - 1) ? -h_l : (h_c - h_l);
        }
        float dv;
        if (gi == 0) dv = v_c;
        else {
            const float v_u = s_w1[c - ES] * s_y1[c - ES];
            dv = (gi == MM - 1) ? -v_u : (v_c - v_u);
        }
        const float xo = s_x[c];
        const float xn = (xo + F_TAU * (dh + dv) + F_LT * s_im[c]) * F_INV_DENOM;
        const int g = gi * NN + gj;
        x_out[g]  = xn;
        xt_out[g] = xn + F_THETA * (xn - xo);
    }
}

extern "C" void kernel_launch(void* const* d_in, const int* in_sizes, int n_in,
                              void* d_out, int out_size) {
    const float* img = (const float*)d_in[0];   // [1, 4096, 4096]
    const float* w   = (const float*)d_in[1];   // [2, 4096, 4096]
    const float* y0  = (const float*)d_in[2];   // [2, 4096, 4096]
    float* out = (float*)d_out;

    dim3 grid(NN / TS, MM / TS);

    for (int k = 0; k < MAX_IT / 2; ++k) {
        const int first = (k == 0);
        const int last  = (k == MAX_IT / 2 - 1);
        const int in_b  = k & 1;
        const int out_b = (k + 1) & 1;
        pd_iter2<<<grid, NTHREADS>>>(first, last, in_b, out_b, img, w, y0, out);
    }
}